// round 15
// baseline (speedup 1.0000x reference)
#include <cuda_runtime.h>
#include <cuda_fp16.h>
#include <cstdint>

// ---------------- problem dims ----------------
#define DIM_M 8192   // B*S
#define DIM_N 16384  // D_OUT
#define DIM_K 4096   // D_IN

static constexpr int BM = 128;
static constexpr int BN = 128;
static constexpr int BK = 64;
static constexpr int M_TILES = DIM_M / BM;   // 64
static constexpr int N_TILES = DIM_N / BN;   // 128
static constexpr int K_TILES = DIM_K / BK;   // 64
static constexpr int STAGES  = 3;

static constexpr int A_BYTES     = BM * BK * 2;          // 16384
static constexpr int B_BYTES     = BN * BK * 2;          // 16384
static constexpr int STAGE_BYTES = A_BYTES + B_BYTES;    // 32768
static constexpr int SMEM_MBAR   = STAGES * STAGE_BYTES; // 98304
static constexpr int SMEM_SB     = SMEM_MBAR + 64;
static constexpr int SMEM_TOTAL  = SMEM_SB + BN * 8;     // 99392 (2 CTAs/SM)

// ---------------- device scratch (static; no dynamic alloc) ----------------
__device__ unsigned short g_wh[(size_t)DIM_N * DIM_K]; // weight as fp16 (exact, |w|<=127)
__device__ unsigned short g_xh[(size_t)DIM_M * DIM_K]; // x rounded to fp16

// ---------------- ptx helpers (non-'a' features only; target is compute_103) ----------------
__device__ __forceinline__ uint32_t smem_u32(const void* p) {
    uint32_t a;
    asm("{ .reg .u64 t; cvta.to.shared.u64 t, %1; cvt.u32.u64 %0, t; }" : "=r"(a) : "l"(p));
    return a;
}
__device__ __forceinline__ void cp_async16(uint32_t dst, const void* src) {
    asm volatile("cp.async.cg.shared.global [%0], [%1], 16;" :: "r"(dst), "l"(src));
}
__device__ __forceinline__ void cp_async_mbar_arrive(uint32_t bar) {
    asm volatile("cp.async.mbarrier.arrive.noinc.shared::cta.b64 [%0];" :: "r"(bar) : "memory");
}
__device__ __forceinline__ void mbar_init(uint32_t bar, uint32_t cnt) {
    asm volatile("mbarrier.init.shared.b64 [%0], %1;" :: "r"(bar), "r"(cnt) : "memory");
}
__device__ __forceinline__ void mbar_wait(uint32_t bar, uint32_t parity) {
    asm volatile(
        "{\n\t.reg .pred P;\n\t"
        "W_%=:\n\t"
        "mbarrier.try_wait.parity.acquire.cta.shared::cta.b64 P, [%0], %1, 0x989680;\n\t"
        "@P bra.uni D_%=;\n\t"
        "bra.uni W_%=;\n\t"
        "D_%=:\n\t}"
        :: "r"(bar), "r"(parity) : "memory");
}
// producer/consumer split barrier: 128 arrives (ks==2) + 128 syncs (ks==3) = 256
__device__ __forceinline__ void bar_arrive_1() {
    asm volatile("bar.arrive 1, 256;" ::: "memory");
}
__device__ __forceinline__ void bar_sync_1() {
    asm volatile("bar.sync 1, 256;" ::: "memory");
}
__device__ __forceinline__ void ldmatrix_x4(uint32_t* r, uint32_t addr) {
    asm volatile("ldmatrix.sync.aligned.m8n8.x4.shared.b16 {%0,%1,%2,%3}, [%4];"
                 : "=r"(r[0]), "=r"(r[1]), "=r"(r[2]), "=r"(r[3]) : "r"(addr));
}
__device__ __forceinline__ void mma16816(float* c, const uint32_t* a, uint32_t b0, uint32_t b1) {
    asm volatile(
        "mma.sync.aligned.m16n8k16.row.col.f32.f16.f16.f32 "
        "{%0,%1,%2,%3}, {%4,%5,%6,%7}, {%8,%9}, {%0,%1,%2,%3};"
        : "+f"(c[0]), "+f"(c[1]), "+f"(c[2]), "+f"(c[3])
        : "r"(a[0]), "r"(a[1]), "r"(a[2]), "r"(a[3]), "r"(b0), "r"(b1));
}
// streaming store (evict-first): output is write-once, keep L2 for operand reuse
__device__ __forceinline__ void stg_cs_f2(float* p, float2 v) {
    asm volatile("st.global.cs.v2.f32 [%0], {%1, %2};" :: "l"(p), "f"(v.x), "f"(v.y) : "memory");
}
// evict-first vector loads: convert inputs are dead after reading
__device__ __forceinline__ int4 ldg_cs_i4(const int4* p) {
    int4 v;
    asm volatile("ld.global.cs.v4.u32 {%0,%1,%2,%3}, [%4];"
                 : "=r"(v.x), "=r"(v.y), "=r"(v.z), "=r"(v.w) : "l"(p));
    return v;
}
__device__ __forceinline__ float4 ldg_cs_f4(const float4* p) {
    float4 v;
    asm volatile("ld.global.cs.v4.f32 {%0,%1,%2,%3}, [%4];"
                 : "=f"(v.x), "=f"(v.y), "=f"(v.z), "=f"(v.w) : "l"(p));
    return v;
}

// ---------------- grid-stride conversion prepass ----------------
// x loop FIRST, w loop LAST, both DESCENDING: the GEMM wave-1 B working set
// (low-index g_wh strips, ~37 MB) is the most recently written data in L2 at
// GEMM launch; evict-first input loads avoid displacing the fp16 outputs.
static constexpr int W_CHUNKS = (int)(((size_t)DIM_N * DIM_K) / 4);
static constexpr int X_CHUNKS = (int)(((size_t)DIM_M * DIM_K) / 4);
static constexpr int CVT_BLOCKS  = 1480;
static constexpr int CVT_THREADS = 256;

__global__ void __launch_bounds__(CVT_THREADS) convert_all_kernel(const int4* __restrict__ w,
                                                                  const float4* __restrict__ x) {
    const int nthreads = CVT_BLOCKS * CVT_THREADS;
    const int t0 = blockIdx.x * CVT_THREADS + threadIdx.x;
    for (int i = X_CHUNKS - 1 - t0; i >= 0; i -= nthreads) {
        float4 v = ldg_cs_f4(x + i);
        __half2 p0 = __floats2half2_rn(v.x, v.y);
        __half2 p1 = __floats2half2_rn(v.z, v.w);
        uint2 o;
        o.x = *reinterpret_cast<unsigned*>(&p0);
        o.y = *reinterpret_cast<unsigned*>(&p1);
        reinterpret_cast<uint2*>(g_xh)[i] = o;
    }
    for (int i = W_CHUNKS - 1 - t0; i >= 0; i -= nthreads) {
        int4 v = ldg_cs_i4(w + i);
        __half2 p0 = __floats2half2_rn((float)v.x, (float)v.y); // exact: |w| <= 127
        __half2 p1 = __floats2half2_rn((float)v.z, (float)v.w);
        uint2 o;
        o.x = *reinterpret_cast<unsigned*>(&p0);
        o.y = *reinterpret_cast<unsigned*>(&p1);
        reinterpret_cast<uint2*>(g_wh)[i] = o;
    }
}

// ---------------- main GEMM: 128x128x64 CTA, 4 warps (64x64 each), 2 CTAs/SM ----------------
__global__ void __launch_bounds__(128, 2)
qlinear_gemm(const __half* __restrict__ A, const __half* __restrict__ Bw,
             const float* __restrict__ scale, const float* __restrict__ bias,
             float* __restrict__ out) {
    extern __shared__ char smem[];
    const uint32_t sbase = smem_u32(smem);
    const int tid  = threadIdx.x;
    const int wid  = tid >> 5;
    const int lane = tid & 31;

    // supertile rasterization: m fast within group of 8 -> consecutive bids share nt
    constexpr int GROUP = 8;
    const int tpg = GROUP * N_TILES;
    const int grp = blockIdx.x / tpg;
    const int rem = blockIdx.x % tpg;
    const int mt  = grp * GROUP + (rem % GROUP);
    const int nt  = rem / GROUP;

    const __half* gA = A  + (size_t)mt * BM * DIM_K;
    const __half* gB = Bw + (size_t)nt * BN * DIM_K;

    // full-stage mbarriers (RAW tracking via cp.async completion)
    if (tid == 0) {
#pragma unroll
        for (int s = 0; s < STAGES; ++s) mbar_init(sbase + SMEM_MBAR + 8 * s, 128);
    }

    // preload scale/bias into smem (visible after in-loop bar.syncs)
    float* ssc = reinterpret_cast<float*>(smem + SMEM_SB);
    float* sbi = ssc + BN;
    {
        int i = tid;  // BN == 128 == blockDim
        ssc[i] = scale[nt * BN + i];
        sbi[i] = bias[nt * BN + i];
    }
    __syncthreads();   // mbarrier init visible before any cp.async.mbarrier.arrive

    // cp.async stage loader: A 1024 16B-chunks + B 1024, 16 per thread, then async arrive
    auto load_stage = [&](int slot, int kt) {
        const uint32_t sa = sbase + slot * STAGE_BYTES;
        const uint32_t sb = sa + A_BYTES;
        const char* ga = (const char*)(gA + (size_t)kt * BK);
        const char* gb = (const char*)(gB + (size_t)kt * BK);
#pragma unroll
        for (int i = 0; i < 8; ++i) {
            int q = tid + i * 128;
            int r = q >> 3, c = q & 7;
            cp_async16(sa + r * 128 + ((c ^ (r & 7)) << 4),
                       ga + (size_t)r * (DIM_K * 2) + c * 16);
        }
#pragma unroll
        for (int i = 0; i < 8; ++i) {
            int q = tid + i * 128;
            int r = q >> 3, c = q & 7;
            cp_async16(sb + r * 128 + ((c ^ (r & 7)) << 4),
                       gb + (size_t)r * (DIM_K * 2) + c * 16);
        }
        cp_async_mbar_arrive(sbase + SMEM_MBAR + 8 * slot);
    };

    // prologue: fill ALL 3 stages
#pragma unroll
    for (int s = 0; s < STAGES; ++s) load_stage(s, s);

    const int wm = wid & 1;   // 2 warps over M (64 rows each)
    const int wn = wid >> 1;  // 2 warps over N (64 cols each)

    float acc[4][8][4];
#pragma unroll
    for (int i = 0; i < 4; ++i)
#pragma unroll
        for (int j = 0; j < 8; ++j)
#pragma unroll
            for (int k = 0; k < 4; ++k) acc[i][j][k] = 0.f;

    uint32_t af[2][4][4];   // A frags: [buf][m16 tile][reg]
    uint32_t bfr[2][4][4];  // B frags: [buf][n16 tile][reg]

    // ldmatrix per-lane addressing (XOR-swizzled, 128B rows)
    const int rowA = wm * 64 + (lane & 15);
    const int hiA  = lane >> 4;
    const int rowB = wn * 64 + (lane & 7) + ((lane >> 4) << 3);
    const int hiB  = (lane >> 3) & 1;

    auto ldsA = [&](int buf, uint32_t sa, int ks) {
#pragma unroll
        for (int mi = 0; mi < 4; ++mi) {
            int r = rowA + mi * 16;
            int c = ks * 2 + hiA;
            ldmatrix_x4(af[buf][mi], sa + r * 128 + ((c ^ (r & 7)) << 4));
        }
    };
    auto ldsB = [&](int buf, uint32_t sb, int ks) {
#pragma unroll
        for (int nf = 0; nf < 4; ++nf) {
            int r = rowB + nf * 16;
            int c = ks * 2 + hiB;
            ldmatrix_x4(bfr[buf][nf], sb + r * 128 + ((c ^ (r & 7)) << 4));
        }
    };

    // wait stage 0 (parity 0), preload its ks=0 fragments
    mbar_wait(sbase + SMEM_MBAR, 0);
    ldsA(0, sbase, 0);
    ldsB(0, sbase + A_BYTES, 0);

    for (int kt = 0; kt < K_TILES; ++kt) {
        const uint32_t sa = sbase + (kt % STAGES) * STAGE_BYTES;
        const uint32_t sb = sa + A_BYTES;
#pragma unroll
        for (int ks = 0; ks < 4; ++ks) {
            const int cur = ks & 1, nxt = cur ^ 1;
            if (ks < 3) {
                ldsA(nxt, sa, ks + 1);
                ldsB(nxt, sb, ks + 1);
                // last read of current slot done -> signal WAR barrier (hidden under ks=3 MMAs)
                if (ks == 2 && kt + 1 < K_TILES) bar_arrive_1();
            } else if (kt + 1 < K_TILES) {
                // WAR: wait everyone's ks==2 arrival (announced one MMA batch ago)
                bar_sync_1();
                if (kt + STAGES < K_TILES) load_stage(kt % STAGES, kt + STAGES);
                // RAW: wait stage kt+1 cp.async completion (covered by sibling warps/CTA)
                const int ns = (kt + 1) % STAGES;
                mbar_wait(sbase + SMEM_MBAR + 8 * ns, ((kt + 1) / STAGES) & 1);
                const uint32_t nsa = sbase + ns * STAGE_BYTES;
                ldsA(nxt, nsa, 0);
                ldsB(nxt, nsa + A_BYTES, 0);
            }
#pragma unroll
            for (int mi = 0; mi < 4; ++mi)
#pragma unroll
                for (int nf = 0; nf < 4; ++nf) {
                    mma16816(acc[mi][nf * 2 + 0], af[cur][mi], bfr[cur][nf][0], bfr[cur][nf][1]);
                    mma16816(acc[mi][nf * 2 + 1], af[cur][mi], bfr[cur][nf][2], bfr[cur][nf][3]);
                }
        }
    }

    // ---- epilogue: scale * acc + bias, streaming (evict-first) float2 stores ----
#pragma unroll
    for (int mi = 0; mi < 4; ++mi) {
        const int m0 = mt * BM + wm * 64 + mi * 16 + (lane >> 2);
        float* orow0 = out + (size_t)m0 * DIM_N + nt * BN;
        float* orow1 = orow0 + (size_t)8 * DIM_N;
#pragma unroll
        for (int j = 0; j < 8; ++j) {
            const int n = wn * 64 + j * 8 + (lane & 3) * 2;
            const float s0 = ssc[n], s1 = ssc[n + 1];
            const float b0 = sbi[n], b1 = sbi[n + 1];
            float2 v0, v1;
            v0.x = fmaf(acc[mi][j][0], s0, b0);
            v0.y = fmaf(acc[mi][j][1], s1, b1);
            v1.x = fmaf(acc[mi][j][2], s0, b0);
            v1.y = fmaf(acc[mi][j][3], s1, b1);
            stg_cs_f2(orow0 + n, v0);
            stg_cs_f2(orow1 + n, v1);
        }
    }
}

// ---------------- host launch ----------------
extern "C" void kernel_launch(void* const* d_in, const int* in_sizes, int n_in,
                              void* d_out, int out_size) {
    const float* x     = (const float*)d_in[0];
    const int*   w     = (const int*)d_in[1];
    const float* scale = (const float*)d_in[2];
    const float* bias  = (const float*)d_in[3];
    float*       out   = (float*)d_out;

    void *p_wh = nullptr, *p_xh = nullptr;
    cudaGetSymbolAddress(&p_wh, g_wh);
    cudaGetSymbolAddress(&p_xh, g_xh);

    convert_all_kernel<<<CVT_BLOCKS, CVT_THREADS>>>((const int4*)w, (const float4*)x);

    cudaFuncSetAttribute(qlinear_gemm, cudaFuncAttributeMaxDynamicSharedMemorySize, SMEM_TOTAL);
    qlinear_gemm<<<M_TILES * N_TILES, 128, SMEM_TOTAL>>>(
        (const __half*)p_xh, (const __half*)p_wh, scale, bias, out);
}

// round 16
// speedup vs baseline: 1.0088x; 1.0088x over previous
#include <cuda_runtime.h>
#include <cuda_fp16.h>
#include <cstdint>

// ---------------- problem dims ----------------
#define DIM_M 8192   // B*S
#define DIM_N 16384  // D_OUT
#define DIM_K 4096   // D_IN

static constexpr int BM = 128;
static constexpr int BN = 128;
static constexpr int BK = 64;
static constexpr int M_TILES = DIM_M / BM;   // 64
static constexpr int N_TILES = DIM_N / BN;   // 128
static constexpr int K_TILES = DIM_K / BK;   // 64
static constexpr int STAGES  = 3;

static constexpr int A_BYTES     = BM * BK * 2;          // 16384
static constexpr int B_BYTES     = BN * BK * 2;          // 16384
static constexpr int STAGE_BYTES = A_BYTES + B_BYTES;    // 32768
static constexpr int SMEM_MBAR   = STAGES * STAGE_BYTES; // 98304
static constexpr int SMEM_SB     = SMEM_MBAR + 64;
static constexpr int SMEM_TOTAL  = SMEM_SB + BN * 8;     // 99392 (2 CTAs/SM)

// ---------------- device scratch (static; no dynamic alloc) ----------------
__device__ unsigned short g_wh[(size_t)DIM_N * DIM_K]; // weight as fp16 (exact, |w|<=127)
__device__ unsigned short g_xh[(size_t)DIM_M * DIM_K]; // x rounded to fp16

// ---------------- ptx helpers (non-'a' features only; target is compute_103) ----------------
__device__ __forceinline__ uint32_t smem_u32(const void* p) {
    uint32_t a;
    asm("{ .reg .u64 t; cvta.to.shared.u64 t, %1; cvt.u32.u64 %0, t; }" : "=r"(a) : "l"(p));
    return a;
}
__device__ __forceinline__ void cp_async16(uint32_t dst, const void* src) {
    asm volatile("cp.async.cg.shared.global [%0], [%1], 16;" :: "r"(dst), "l"(src));
}
__device__ __forceinline__ void cp_async_mbar_arrive(uint32_t bar) {
    asm volatile("cp.async.mbarrier.arrive.noinc.shared::cta.b64 [%0];" :: "r"(bar) : "memory");
}
__device__ __forceinline__ void mbar_init(uint32_t bar, uint32_t cnt) {
    asm volatile("mbarrier.init.shared.b64 [%0], %1;" :: "r"(bar), "r"(cnt) : "memory");
}
__device__ __forceinline__ void mbar_wait(uint32_t bar, uint32_t parity) {
    asm volatile(
        "{\n\t.reg .pred P;\n\t"
        "W_%=:\n\t"
        "mbarrier.try_wait.parity.acquire.cta.shared::cta.b64 P, [%0], %1, 0x989680;\n\t"
        "@P bra.uni D_%=;\n\t"
        "bra.uni W_%=;\n\t"
        "D_%=:\n\t}"
        :: "r"(bar), "r"(parity) : "memory");
}
// producer/consumer split barrier: 128 arrives (ks==2) + 128 syncs (ks==3) = 256
__device__ __forceinline__ void bar_arrive_1() {
    asm volatile("bar.arrive 1, 256;" ::: "memory");
}
__device__ __forceinline__ void bar_sync_1() {
    asm volatile("bar.sync 1, 256;" ::: "memory");
}
__device__ __forceinline__ void ldmatrix_x4(uint32_t* r, uint32_t addr) {
    asm volatile("ldmatrix.sync.aligned.m8n8.x4.shared.b16 {%0,%1,%2,%3}, [%4];"
                 : "=r"(r[0]), "=r"(r[1]), "=r"(r[2]), "=r"(r[3]) : "r"(addr));
}
__device__ __forceinline__ void mma16816(float* c, const uint32_t* a, uint32_t b0, uint32_t b1) {
    asm volatile(
        "mma.sync.aligned.m16n8k16.row.col.f32.f16.f16.f32 "
        "{%0,%1,%2,%3}, {%4,%5,%6,%7}, {%8,%9}, {%0,%1,%2,%3};"
        : "+f"(c[0]), "+f"(c[1]), "+f"(c[2]), "+f"(c[3])
        : "r"(a[0]), "r"(a[1]), "r"(a[2]), "r"(a[3]), "r"(b0), "r"(b1));
}
// streaming store (evict-first): output is write-once, keep L2 for operand reuse
__device__ __forceinline__ void stg_cs_f2(float* p, float2 v) {
    asm volatile("st.global.cs.v2.f32 [%0], {%1, %2};" :: "l"(p), "f"(v.x), "f"(v.y) : "memory");
}

// ---------------- grid-stride conversion prepass (fat threads, high MLP) ----------------
// Loops run DESCENDING so the lowest-index rows (read first by GEMM wave 1:
// A tiles mt 0..7, B strips nt 0..36) are the most recently written -> L2-warm.
static constexpr int W_CHUNKS = (int)(((size_t)DIM_N * DIM_K) / 4);
static constexpr int X_CHUNKS = (int)(((size_t)DIM_M * DIM_K) / 4);
static constexpr int CVT_BLOCKS  = 1480;
static constexpr int CVT_THREADS = 256;

__global__ void __launch_bounds__(CVT_THREADS) convert_all_kernel(const int4* __restrict__ w,
                                                                  const float4* __restrict__ x) {
    const int nthreads = CVT_BLOCKS * CVT_THREADS;
    const int t0 = blockIdx.x * CVT_THREADS + threadIdx.x;
    for (int i = W_CHUNKS - 1 - t0; i >= 0; i -= nthreads) {
        int4 v = w[i];
        __half2 p0 = __floats2half2_rn((float)v.x, (float)v.y); // exact: |w| <= 127
        __half2 p1 = __floats2half2_rn((float)v.z, (float)v.w);
        uint2 o;
        o.x = *reinterpret_cast<unsigned*>(&p0);
        o.y = *reinterpret_cast<unsigned*>(&p1);
        reinterpret_cast<uint2*>(g_wh)[i] = o;
    }
    for (int i = X_CHUNKS - 1 - t0; i >= 0; i -= nthreads) {
        float4 v = x[i];
        __half2 p0 = __floats2half2_rn(v.x, v.y);
        __half2 p1 = __floats2half2_rn(v.z, v.w);
        uint2 o;
        o.x = *reinterpret_cast<unsigned*>(&p0);
        o.y = *reinterpret_cast<unsigned*>(&p1);
        reinterpret_cast<uint2*>(g_xh)[i] = o;
    }
}

// ---------------- main GEMM: 128x128x64 CTA, 4 warps (64x64 each), 2 CTAs/SM ----------------
__global__ void __launch_bounds__(128, 2)
qlinear_gemm(const __half* __restrict__ A, const __half* __restrict__ Bw,
             const float* __restrict__ scale, const float* __restrict__ bias,
             float* __restrict__ out) {
    extern __shared__ char smem[];
    const uint32_t sbase = smem_u32(smem);
    const int tid  = threadIdx.x;
    const int wid  = tid >> 5;
    const int lane = tid & 31;

    // supertile rasterization: m fast within group of 8 -> consecutive bids share nt
    constexpr int GROUP = 8;
    const int tpg = GROUP * N_TILES;
    const int grp = blockIdx.x / tpg;
    const int rem = blockIdx.x % tpg;
    const int mt  = grp * GROUP + (rem % GROUP);
    const int nt  = rem / GROUP;

    const __half* gA = A  + (size_t)mt * BM * DIM_K;
    const __half* gB = Bw + (size_t)nt * BN * DIM_K;

    // full-stage mbarriers (RAW tracking via cp.async completion)
    if (tid == 0) {
#pragma unroll
        for (int s = 0; s < STAGES; ++s) mbar_init(sbase + SMEM_MBAR + 8 * s, 128);
    }

    // preload scale/bias into smem (visible after in-loop bar.syncs)
    float* ssc = reinterpret_cast<float*>(smem + SMEM_SB);
    float* sbi = ssc + BN;
    {
        int i = tid;  // BN == 128 == blockDim
        ssc[i] = scale[nt * BN + i];
        sbi[i] = bias[nt * BN + i];
    }
    __syncthreads();   // mbarrier init visible before any cp.async.mbarrier.arrive

    // cp.async stage loader: A 1024 16B-chunks + B 1024, 16 per thread, then async arrive
    auto load_stage = [&](int slot, int kt) {
        const uint32_t sa = sbase + slot * STAGE_BYTES;
        const uint32_t sb = sa + A_BYTES;
        const char* ga = (const char*)(gA + (size_t)kt * BK);
        const char* gb = (const char*)(gB + (size_t)kt * BK);
#pragma unroll
        for (int i = 0; i < 8; ++i) {
            int q = tid + i * 128;
            int r = q >> 3, c = q & 7;
            cp_async16(sa + r * 128 + ((c ^ (r & 7)) << 4),
                       ga + (size_t)r * (DIM_K * 2) + c * 16);
        }
#pragma unroll
        for (int i = 0; i < 8; ++i) {
            int q = tid + i * 128;
            int r = q >> 3, c = q & 7;
            cp_async16(sb + r * 128 + ((c ^ (r & 7)) << 4),
                       gb + (size_t)r * (DIM_K * 2) + c * 16);
        }
        cp_async_mbar_arrive(sbase + SMEM_MBAR + 8 * slot);
    };

    // prologue: fill ALL 3 stages
#pragma unroll
    for (int s = 0; s < STAGES; ++s) load_stage(s, s);

    const int wm = wid & 1;   // 2 warps over M (64 rows each)
    const int wn = wid >> 1;  // 2 warps over N (64 cols each)

    float acc[4][8][4];
#pragma unroll
    for (int i = 0; i < 4; ++i)
#pragma unroll
        for (int j = 0; j < 8; ++j)
#pragma unroll
            for (int k = 0; k < 4; ++k) acc[i][j][k] = 0.f;

    uint32_t af[2][4][4];   // A frags: [buf][m16 tile][reg]
    uint32_t bfr[2][4][4];  // B frags: [buf][n16 tile][reg]

    // ldmatrix per-lane addressing (XOR-swizzled, 128B rows)
    const int rowA = wm * 64 + (lane & 15);
    const int hiA  = lane >> 4;
    const int rowB = wn * 64 + (lane & 7) + ((lane >> 4) << 3);
    const int hiB  = (lane >> 3) & 1;

    auto ldsA = [&](int buf, uint32_t sa, int ks) {
#pragma unroll
        for (int mi = 0; mi < 4; ++mi) {
            int r = rowA + mi * 16;
            int c = ks * 2 + hiA;
            ldmatrix_x4(af[buf][mi], sa + r * 128 + ((c ^ (r & 7)) << 4));
        }
    };
    auto ldsB = [&](int buf, uint32_t sb, int ks) {
#pragma unroll
        for (int nf = 0; nf < 4; ++nf) {
            int r = rowB + nf * 16;
            int c = ks * 2 + hiB;
            ldmatrix_x4(bfr[buf][nf], sb + r * 128 + ((c ^ (r & 7)) << 4));
        }
    };

    // wait stage 0 (parity 0), preload its ks=0 fragments
    mbar_wait(sbase + SMEM_MBAR, 0);
    ldsA(0, sbase, 0);
    ldsB(0, sbase + A_BYTES, 0);

    for (int kt = 0; kt < K_TILES; ++kt) {
        const uint32_t sa = sbase + (kt % STAGES) * STAGE_BYTES;
        const uint32_t sb = sa + A_BYTES;
#pragma unroll
        for (int ks = 0; ks < 4; ++ks) {
            const int cur = ks & 1, nxt = cur ^ 1;
            if (ks < 3) {
                ldsA(nxt, sa, ks + 1);
                ldsB(nxt, sb, ks + 1);
                // last read of current slot done -> signal WAR barrier (hidden under ks=3 MMAs)
                if (ks == 2 && kt + 1 < K_TILES) bar_arrive_1();
            } else if (kt + 1 < K_TILES) {
                // WAR: wait everyone's ks==2 arrival (announced one MMA batch ago)
                bar_sync_1();
                if (kt + STAGES < K_TILES) load_stage(kt % STAGES, kt + STAGES);
                // RAW: wait stage kt+1 cp.async completion (covered by sibling warps/CTA)
                const int ns = (kt + 1) % STAGES;
                mbar_wait(sbase + SMEM_MBAR + 8 * ns, ((kt + 1) / STAGES) & 1);
                const uint32_t nsa = sbase + ns * STAGE_BYTES;
                ldsA(nxt, nsa, 0);
                ldsB(nxt, nsa + A_BYTES, 0);
            }
#pragma unroll
            for (int mi = 0; mi < 4; ++mi)
#pragma unroll
                for (int nf = 0; nf < 4; ++nf) {
                    mma16816(acc[mi][nf * 2 + 0], af[cur][mi], bfr[cur][nf][0], bfr[cur][nf][1]);
                    mma16816(acc[mi][nf * 2 + 1], af[cur][mi], bfr[cur][nf][2], bfr[cur][nf][3]);
                }
        }
    }

    // ---- epilogue: scale * acc + bias, streaming (evict-first) float2 stores ----
#pragma unroll
    for (int mi = 0; mi < 4; ++mi) {
        const int m0 = mt * BM + wm * 64 + mi * 16 + (lane >> 2);
        float* orow0 = out + (size_t)m0 * DIM_N + nt * BN;
        float* orow1 = orow0 + (size_t)8 * DIM_N;
#pragma unroll
        for (int j = 0; j < 8; ++j) {
            const int n = wn * 64 + j * 8 + (lane & 3) * 2;
            const float s0 = ssc[n], s1 = ssc[n + 1];
            const float b0 = sbi[n], b1 = sbi[n + 1];
            float2 v0, v1;
            v0.x = fmaf(acc[mi][j][0], s0, b0);
            v0.y = fmaf(acc[mi][j][1], s1, b1);
            v1.x = fmaf(acc[mi][j][2], s0, b0);
            v1.y = fmaf(acc[mi][j][3], s1, b1);
            stg_cs_f2(orow0 + n, v0);
            stg_cs_f2(orow1 + n, v1);
        }
    }
}

// ---------------- host launch ----------------
extern "C" void kernel_launch(void* const* d_in, const int* in_sizes, int n_in,
                              void* d_out, int out_size) {
    const float* x     = (const float*)d_in[0];
    const int*   w     = (const int*)d_in[1];
    const float* scale = (const float*)d_in[2];
    const float* bias  = (const float*)d_in[3];
    float*       out   = (float*)d_out;

    void *p_wh = nullptr, *p_xh = nullptr;
    cudaGetSymbolAddress(&p_wh, g_wh);
    cudaGetSymbolAddress(&p_xh, g_xh);

    convert_all_kernel<<<CVT_BLOCKS, CVT_THREADS>>>((const int4*)w, (const float4*)x);

    cudaFuncSetAttribute(qlinear_gemm, cudaFuncAttributeMaxDynamicSharedMemorySize, SMEM_TOTAL);
    qlinear_gemm<<<M_TILES * N_TILES, 128, SMEM_TOTAL>>>(
        (const __half*)p_xh, (const __half*)p_wh, scale, bias, out);
}

// round 17
// speedup vs baseline: 1.0100x; 1.0011x over previous
#include <cuda_runtime.h>
#include <cuda_fp16.h>
#include <cstdint>

// ---------------- problem dims ----------------
#define DIM_M 8192   // B*S
#define DIM_N 16384  // D_OUT
#define DIM_K 4096   // D_IN

static constexpr int BM = 128;
static constexpr int BN = 128;
static constexpr int BK = 64;
static constexpr int M_TILES = DIM_M / BM;   // 64
static constexpr int N_TILES = DIM_N / BN;   // 128
static constexpr int K_TILES = DIM_K / BK;   // 64
static constexpr int STAGES  = 3;

static constexpr int A_BYTES     = BM * BK * 2;          // 16384
static constexpr int B_BYTES     = BN * BK * 2;          // 16384
static constexpr int STAGE_BYTES = A_BYTES + B_BYTES;    // 32768
static constexpr int SMEM_MBAR   = STAGES * STAGE_BYTES; // 98304
static constexpr int SMEM_SB     = SMEM_MBAR + 64;
static constexpr int SMEM_TOTAL  = SMEM_SB + BN * 8;     // 99392 (2 CTAs/SM)

// ---------------- device scratch (static; no dynamic alloc) ----------------
__device__ unsigned short g_wh[(size_t)DIM_N * DIM_K]; // weight as fp16 (exact, |w|<=127)
__device__ unsigned short g_xh[(size_t)DIM_M * DIM_K]; // x rounded to fp16

// ---------------- ptx helpers (non-'a' features only; target is compute_103) ----------------
__device__ __forceinline__ uint32_t smem_u32(const void* p) {
    uint32_t a;
    asm("{ .reg .u64 t; cvta.to.shared.u64 t, %1; cvt.u32.u64 %0, t; }" : "=r"(a) : "l"(p));
    return a;
}
__device__ __forceinline__ void cp_async16(uint32_t dst, const void* src) {
    asm volatile("cp.async.cg.shared.global [%0], [%1], 16;" :: "r"(dst), "l"(src));
}
__device__ __forceinline__ void cp_async_mbar_arrive(uint32_t bar) {
    asm volatile("cp.async.mbarrier.arrive.noinc.shared::cta.b64 [%0];" :: "r"(bar) : "memory");
}
__device__ __forceinline__ void mbar_init(uint32_t bar, uint32_t cnt) {
    asm volatile("mbarrier.init.shared.b64 [%0], %1;" :: "r"(bar), "r"(cnt) : "memory");
}
__device__ __forceinline__ void mbar_wait(uint32_t bar, uint32_t parity) {
    asm volatile(
        "{\n\t.reg .pred P;\n\t"
        "W_%=:\n\t"
        "mbarrier.try_wait.parity.acquire.cta.shared::cta.b64 P, [%0], %1, 0x989680;\n\t"
        "@P bra.uni D_%=;\n\t"
        "bra.uni W_%=;\n\t"
        "D_%=:\n\t}"
        :: "r"(bar), "r"(parity) : "memory");
}
// producer/consumer split barrier: 128 arrives (ks==2) + 128 syncs (ks==3) = 256
__device__ __forceinline__ void bar_arrive_1() {
    asm volatile("bar.arrive 1, 256;" ::: "memory");
}
__device__ __forceinline__ void bar_sync_1() {
    asm volatile("bar.sync 1, 256;" ::: "memory");
}
__device__ __forceinline__ void ldmatrix_x4(uint32_t* r, uint32_t addr) {
    asm volatile("ldmatrix.sync.aligned.m8n8.x4.shared.b16 {%0,%1,%2,%3}, [%4];"
                 : "=r"(r[0]), "=r"(r[1]), "=r"(r[2]), "=r"(r[3]) : "r"(addr));
}
__device__ __forceinline__ void mma16816(float* c, const uint32_t* a, uint32_t b0, uint32_t b1) {
    asm volatile(
        "mma.sync.aligned.m16n8k16.row.col.f32.f16.f16.f32 "
        "{%0,%1,%2,%3}, {%4,%5,%6,%7}, {%8,%9}, {%0,%1,%2,%3};"
        : "+f"(c[0]), "+f"(c[1]), "+f"(c[2]), "+f"(c[3])
        : "r"(a[0]), "r"(a[1]), "r"(a[2]), "r"(a[3]), "r"(b0), "r"(b1));
}
// streaming store (evict-first): output is write-once, keep L2 for operand reuse
__device__ __forceinline__ void stg_cs_f2(float* p, float2 v) {
    asm volatile("st.global.cs.v2.f32 [%0], {%1, %2};" :: "l"(p), "f"(v.x), "f"(v.y) : "memory");
}

// ---------------- grid-stride conversion prepass ----------------
// CVT_BLOCKS = 1184 = 8 blocks/SM x 148 SMs = EXACTLY one resident wave
// (2048-thread/SM cap). 1480 left 296 straggler blocks queuing behind wave 1,
// costing ~15-20us of load-imbalance tail on a bandwidth-floor kernel.
// Loops DESCENDING so low-index rows (GEMM wave-1 working set) end L2-warm.
static constexpr int W_CHUNKS = (int)(((size_t)DIM_N * DIM_K) / 4);
static constexpr int X_CHUNKS = (int)(((size_t)DIM_M * DIM_K) / 4);
static constexpr int CVT_BLOCKS  = 1184;   // 8/SM: single perfectly-balanced wave
static constexpr int CVT_THREADS = 256;

__global__ void __launch_bounds__(CVT_THREADS) convert_all_kernel(const int4* __restrict__ w,
                                                                  const float4* __restrict__ x) {
    const int nthreads = CVT_BLOCKS * CVT_THREADS;
    const int t0 = blockIdx.x * CVT_THREADS + threadIdx.x;
    for (int i = W_CHUNKS - 1 - t0; i >= 0; i -= nthreads) {
        int4 v = w[i];
        __half2 p0 = __floats2half2_rn((float)v.x, (float)v.y); // exact: |w| <= 127
        __half2 p1 = __floats2half2_rn((float)v.z, (float)v.w);
        uint2 o;
        o.x = *reinterpret_cast<unsigned*>(&p0);
        o.y = *reinterpret_cast<unsigned*>(&p1);
        reinterpret_cast<uint2*>(g_wh)[i] = o;
    }
    for (int i = X_CHUNKS - 1 - t0; i >= 0; i -= nthreads) {
        float4 v = x[i];
        __half2 p0 = __floats2half2_rn(v.x, v.y);
        __half2 p1 = __floats2half2_rn(v.z, v.w);
        uint2 o;
        o.x = *reinterpret_cast<unsigned*>(&p0);
        o.y = *reinterpret_cast<unsigned*>(&p1);
        reinterpret_cast<uint2*>(g_xh)[i] = o;
    }
}

// ---------------- main GEMM: 128x128x64 CTA, 4 warps (64x64 each), 2 CTAs/SM ----------------
__global__ void __launch_bounds__(128, 2)
qlinear_gemm(const __half* __restrict__ A, const __half* __restrict__ Bw,
             const float* __restrict__ scale, const float* __restrict__ bias,
             float* __restrict__ out) {
    extern __shared__ char smem[];
    const uint32_t sbase = smem_u32(smem);
    const int tid  = threadIdx.x;
    const int wid  = tid >> 5;
    const int lane = tid & 31;

    // supertile rasterization: m fast within group of 8 -> consecutive bids share nt
    constexpr int GROUP = 8;
    const int tpg = GROUP * N_TILES;
    const int grp = blockIdx.x / tpg;
    const int rem = blockIdx.x % tpg;
    const int mt  = grp * GROUP + (rem % GROUP);
    const int nt  = rem / GROUP;

    const __half* gA = A  + (size_t)mt * BM * DIM_K;
    const __half* gB = Bw + (size_t)nt * BN * DIM_K;

    // full-stage mbarriers (RAW tracking via cp.async completion)
    if (tid == 0) {
#pragma unroll
        for (int s = 0; s < STAGES; ++s) mbar_init(sbase + SMEM_MBAR + 8 * s, 128);
    }

    // preload scale/bias into smem (visible after in-loop bar.syncs)
    float* ssc = reinterpret_cast<float*>(smem + SMEM_SB);
    float* sbi = ssc + BN;
    {
        int i = tid;  // BN == 128 == blockDim
        ssc[i] = scale[nt * BN + i];
        sbi[i] = bias[nt * BN + i];
    }
    __syncthreads();   // mbarrier init visible before any cp.async.mbarrier.arrive

    // cp.async stage loader: A 1024 16B-chunks + B 1024, 16 per thread, then async arrive
    auto load_stage = [&](int slot, int kt) {
        const uint32_t sa = sbase + slot * STAGE_BYTES;
        const uint32_t sb = sa + A_BYTES;
        const char* ga = (const char*)(gA + (size_t)kt * BK);
        const char* gb = (const char*)(gB + (size_t)kt * BK);
#pragma unroll
        for (int i = 0; i < 8; ++i) {
            int q = tid + i * 128;
            int r = q >> 3, c = q & 7;
            cp_async16(sa + r * 128 + ((c ^ (r & 7)) << 4),
                       ga + (size_t)r * (DIM_K * 2) + c * 16);
        }
#pragma unroll
        for (int i = 0; i < 8; ++i) {
            int q = tid + i * 128;
            int r = q >> 3, c = q & 7;
            cp_async16(sb + r * 128 + ((c ^ (r & 7)) << 4),
                       gb + (size_t)r * (DIM_K * 2) + c * 16);
        }
        cp_async_mbar_arrive(sbase + SMEM_MBAR + 8 * slot);
    };

    // prologue: fill ALL 3 stages
#pragma unroll
    for (int s = 0; s < STAGES; ++s) load_stage(s, s);

    const int wm = wid & 1;   // 2 warps over M (64 rows each)
    const int wn = wid >> 1;  // 2 warps over N (64 cols each)

    float acc[4][8][4];
#pragma unroll
    for (int i = 0; i < 4; ++i)
#pragma unroll
        for (int j = 0; j < 8; ++j)
#pragma unroll
            for (int k = 0; k < 4; ++k) acc[i][j][k] = 0.f;

    uint32_t af[2][4][4];   // A frags: [buf][m16 tile][reg]
    uint32_t bfr[2][4][4];  // B frags: [buf][n16 tile][reg]

    // ldmatrix per-lane addressing (XOR-swizzled, 128B rows)
    const int rowA = wm * 64 + (lane & 15);
    const int hiA  = lane >> 4;
    const int rowB = wn * 64 + (lane & 7) + ((lane >> 4) << 3);
    const int hiB  = (lane >> 3) & 1;

    auto ldsA = [&](int buf, uint32_t sa, int ks) {
#pragma unroll
        for (int mi = 0; mi < 4; ++mi) {
            int r = rowA + mi * 16;
            int c = ks * 2 + hiA;
            ldmatrix_x4(af[buf][mi], sa + r * 128 + ((c ^ (r & 7)) << 4));
        }
    };
    auto ldsB = [&](int buf, uint32_t sb, int ks) {
#pragma unroll
        for (int nf = 0; nf < 4; ++nf) {
            int r = rowB + nf * 16;
            int c = ks * 2 + hiB;
            ldmatrix_x4(bfr[buf][nf], sb + r * 128 + ((c ^ (r & 7)) << 4));
        }
    };

    // wait stage 0 (parity 0), preload its ks=0 fragments
    mbar_wait(sbase + SMEM_MBAR, 0);
    ldsA(0, sbase, 0);
    ldsB(0, sbase + A_BYTES, 0);

    for (int kt = 0; kt < K_TILES; ++kt) {
        const uint32_t sa = sbase + (kt % STAGES) * STAGE_BYTES;
        const uint32_t sb = sa + A_BYTES;
#pragma unroll
        for (int ks = 0; ks < 4; ++ks) {
            const int cur = ks & 1, nxt = cur ^ 1;
            if (ks < 3) {
                ldsA(nxt, sa, ks + 1);
                ldsB(nxt, sb, ks + 1);
                // last read of current slot done -> signal WAR barrier (hidden under ks=3 MMAs)
                if (ks == 2 && kt + 1 < K_TILES) bar_arrive_1();
            } else if (kt + 1 < K_TILES) {
                // WAR: wait everyone's ks==2 arrival (announced one MMA batch ago)
                bar_sync_1();
                if (kt + STAGES < K_TILES) load_stage(kt % STAGES, kt + STAGES);
                // RAW: wait stage kt+1 cp.async completion (covered by sibling warps/CTA)
                const int ns = (kt + 1) % STAGES;
                mbar_wait(sbase + SMEM_MBAR + 8 * ns, ((kt + 1) / STAGES) & 1);
                const uint32_t nsa = sbase + ns * STAGE_BYTES;
                ldsA(nxt, nsa, 0);
                ldsB(nxt, nsa + A_BYTES, 0);
            }
#pragma unroll
            for (int mi = 0; mi < 4; ++mi)
#pragma unroll
                for (int nf = 0; nf < 4; ++nf) {
                    mma16816(acc[mi][nf * 2 + 0], af[cur][mi], bfr[cur][nf][0], bfr[cur][nf][1]);
                    mma16816(acc[mi][nf * 2 + 1], af[cur][mi], bfr[cur][nf][2], bfr[cur][nf][3]);
                }
        }
    }

    // ---- epilogue: scale * acc + bias, streaming (evict-first) float2 stores ----
#pragma unroll
    for (int mi = 0; mi < 4; ++mi) {
        const int m0 = mt * BM + wm * 64 + mi * 16 + (lane >> 2);
        float* orow0 = out + (size_t)m0 * DIM_N + nt * BN;
        float* orow1 = orow0 + (size_t)8 * DIM_N;
#pragma unroll
        for (int j = 0; j < 8; ++j) {
            const int n = wn * 64 + j * 8 + (lane & 3) * 2;
            const float s0 = ssc[n], s1 = ssc[n + 1];
            const float b0 = sbi[n], b1 = sbi[n + 1];
            float2 v0, v1;
            v0.x = fmaf(acc[mi][j][0], s0, b0);
            v0.y = fmaf(acc[mi][j][1], s1, b1);
            v1.x = fmaf(acc[mi][j][2], s0, b0);
            v1.y = fmaf(acc[mi][j][3], s1, b1);
            stg_cs_f2(orow0 + n, v0);
            stg_cs_f2(orow1 + n, v1);
        }
    }
}

// ---------------- host launch ----------------
extern "C" void kernel_launch(void* const* d_in, const int* in_sizes, int n_in,
                              void* d_out, int out_size) {
    const float* x     = (const float*)d_in[0];
    const int*   w     = (const int*)d_in[1];
    const float* scale = (const float*)d_in[2];
    const float* bias  = (const float*)d_in[3];
    float*       out   = (float*)d_out;

    void *p_wh = nullptr, *p_xh = nullptr;
    cudaGetSymbolAddress(&p_wh, g_wh);
    cudaGetSymbolAddress(&p_xh, g_xh);

    convert_all_kernel<<<CVT_BLOCKS, CVT_THREADS>>>((const int4*)w, (const float4*)x);

    cudaFuncSetAttribute(qlinear_gemm, cudaFuncAttributeMaxDynamicSharedMemorySize, SMEM_TOTAL);
    qlinear_gemm<<<M_TILES * N_TILES, 128, SMEM_TOTAL>>>(
        (const __half*)p_xh, (const __half*)p_wh, scale, bias, out);
}